// round 10
// baseline (speedup 1.0000x reference)
#include <cuda_runtime.h>
#include <cstdint>

// HybridLoss: smooth_l1(preds,targets) + 0.5*(1 - mean(box_overlap))
// preds, targets: [2000000, 10] float32 row-major. Output: 1 float scalar.
//
// cp.async (LDGSTS) 5-stage smem multibuffer, issue-before-wait pipeline.
// 256 thr/CTA, 256 rows/tile, 4 CTA/SM (592 CTAs, one wave, 32 warps/SM).

#define NROWS 2000000
#define THREADS 256
#define NBLOCKS 592                                   // 148 SMs * 4 CTAs
#define STAGES 5
#define TILE_ROWS 256
#define ABYTES (TILE_ROWS * 40)                       // 10240 B per array
#define STAGE_BYTES (2 * ABYTES)                      // 20480 B... (see note) actually 2*10240
#define NTILES ((NROWS + TILE_ROWS - 1) / TILE_ROWS)  // 7813 (last tile 128 rows)
#define SMEM_DYN (STAGES * STAGE_BYTES)               // 5 * 20480 = 102400? -> too big
// NOTE: STAGE holds preds+targets halves; 20480B * 5 = 102400B exceeds budget.
// Use TILE_ROWS=128 per-thread-pair instead? No: keep 256 rows but stage bytes
// = 2*10240 = 20480 -> reduce STAGES to 5 won't fit 4 CTA. Recompute:
// We want 4 CTA/SM: smem/CTA <= ~56KB. STAGES=5 of 10240B total (5120B per
// array, 128 rows) -> tile=128 rows with 256 threads = 2 ROWS PER... no.
// Final layout chosen: TILE_ROWS=256, stage=20480B, STAGES=2.5 no.
// => Decision: TILE_ROWS=256, 256 thr, STAGES=5, but stage holds only rows
// for this CTA: 256 rows * 80B = 20480B. smem = 5*20480 = 100KB -> 2 CTA/SM.
// That loses occupancy. Instead: TILE_ROWS=128 with 256 threads consuming
// HALF tile each? Simpler: 2 tiles consumed per iteration.
// ---- Actual implemented config (supersedes macros above): ----
#undef TILE_ROWS
#undef ABYTES
#undef STAGE_BYTES
#undef NTILES
#undef SMEM_DYN
#define TILE_ROWS 128                                  // rows per stage
#define ABYTES (TILE_ROWS * 40)                        // 5120 B per array
#define STAGE_BYTES (2 * ABYTES)                       // 10240 B
#define NTILES (NROWS / TILE_ROWS)                     // 15625 exact
#define SMEM_DYN (STAGES * STAGE_BYTES)                // 51200 B -> 4 CTA/SM
#define CHUNKS (STAGE_BYTES / 16)                      // 640
#define EPSF 1e-6f

__device__ double g_acc[2] = {0.0, 0.0};
__device__ unsigned int g_ticket = 0;

__device__ __forceinline__ uint32_t smem_u32(const void* p) {
    return (uint32_t)__cvta_generic_to_shared(p);
}
__device__ __forceinline__ void cp16(uint32_t dst, const void* src) {
    asm volatile("cp.async.cg.shared.global [%0], [%1], 16;" :: "r"(dst), "l"(src));
}
__device__ __forceinline__ void cp_commit() {
    asm volatile("cp.async.commit_group;" ::: "memory");
}
template <int N>
__device__ __forceinline__ void cp_wait_group() {
    asm volatile("cp.async.wait_group %0;" :: "n"(N) : "memory");
}

// Issue one stage's 640 16B chunks across 256 threads (2.5 each -> 3 w/guard).
__device__ __forceinline__ void issue_stage(char* stage_base,
                                            const char* __restrict__ preds,
                                            const char* __restrict__ targets,
                                            int tile, int tid)
{
    const char* psrc = preds   + (size_t)tile * ABYTES;
    const char* tsrc = targets + (size_t)tile * ABYTES;
    const uint32_t dst0 = smem_u32(stage_base);
    #pragma unroll
    for (int j = 0; j < 3; j++) {
        int idx = tid + j * THREADS;                  // 0..767, valid < 640
        if (idx < CHUNKS) {
            const char* src = (idx < CHUNKS/2) ? (psrc + (size_t)idx * 16)
                                               : (tsrc + (size_t)(idx - CHUNKS/2) * 16);
            cp16(dst0 + (uint32_t)idx * 16, src);
        }
    }
}

__device__ __forceinline__ void row_math(const char* __restrict__ prow,
                                         const char* __restrict__ trow,
                                         float& l1_acc, float& ov_acc)
{
    float p[10], t[10];
    const float2* rp = reinterpret_cast<const float2*>(prow);
    const float2* rt = reinterpret_cast<const float2*>(trow);
    #pragma unroll
    for (int j = 0; j < 5; j++) {
        float2 a = rp[j]; p[2*j] = a.x; p[2*j+1] = a.y;
        float2 b = rt[j]; t[2*j] = b.x; t[2*j+1] = b.y;
    }

    // smooth L1, select-free
    #pragma unroll
    for (int j = 0; j < 10; j++) {
        float d  = p[j] - t[j];
        float ad = fabsf(d);
        float m  = fminf(ad, 1.0f);
        l1_acc = fmaf(m, fmaf(-0.5f, m, ad), l1_acc);
    }

    // raw quaternions (no normalization)
    const float px = p[6], py = p[7], pz = p[8], pw = p[9];
    const float gx = t[6], gy = t[7], gz = t[8], gw = t[9];
    const float Ap = px*px + py*py + pz*pz + pw*pw;
    const float Ag = gx*gx + gy*gy + gz*gz + gw*gw;
    const float rpg = __fdividef(1.0f, Ap * Ag);
    const float sp  = 0.5f * Ag * rpg;   // 0.5/Ap
    const float sg  = 0.5f * Ap * rpg;   // 0.5/Ag

    const float dq = px*gx + py*gy + pz*gz + pw*gw;
    const float rot_align = fmaxf(fmaf(4.0f * dq * dq, rpg, -1.0f) * (1.0f/3.0f), 0.0f);

    const float dpx = p[3], dpy = p[4], dpz = p[5];
    const float dgx = t[3], dgy = t[4], dgz = t[5];

    float num = 1.0f, den = 1.0f;
    {
        float mp = (Ap - 2.0f*(py*py + pz*pz))*dpx + 2.0f*(px*py + pz*pw)*dpy + 2.0f*(px*pz - py*pw)*dpz;
        float mg = (Ag - 2.0f*(gy*gy + gz*gz))*dgx + 2.0f*(gx*gy + gz*gw)*dgy + 2.0f*(gx*gz - gy*gw)*dgz;
        float pe = sp * fabsf(mp), ge = sg * fabsf(mg);
        float cd = fabsf(p[0] - t[0]);
        num *= fmaxf(2.0f * fminf(pe, ge) - cd, 0.0f);
        den *= pe + ge + EPSF;
    }
    {
        float mp = 2.0f*(px*py - pz*pw)*dpx + (Ap - 2.0f*(px*px + pz*pz))*dpy + 2.0f*(py*pz + px*pw)*dpz;
        float mg = 2.0f*(gx*gy - gz*gw)*dgx + (Ag - 2.0f*(gx*gx + gz*gz))*dgy + 2.0f*(gy*gz + gx*gw)*dgz;
        float pe = sp * fabsf(mp), ge = sg * fabsf(mg);
        float cd = fabsf(p[1] - t[1]);
        num *= fmaxf(2.0f * fminf(pe, ge) - cd, 0.0f);
        den *= pe + ge + EPSF;
    }
    {
        float mp = 2.0f*(px*pz + py*pw)*dpx + 2.0f*(py*pz - px*pw)*dpy + (Ap - 2.0f*(px*px + py*py))*dpz;
        float mg = 2.0f*(gx*gz + gy*gw)*dgx + 2.0f*(gy*gz - gx*gw)*dgy + (Ag - 2.0f*(gx*gx + gy*gy))*dgz;
        float pe = sp * fabsf(mp), ge = sg * fabsf(mg);
        float cd = fabsf(p[2] - t[2]);
        num *= fmaxf(2.0f * fminf(pe, ge) - cd, 0.0f);
        den *= pe + ge + EPSF;
    }
    ov_acc += __fdividef(num * rot_align, den);
}

__global__ __launch_bounds__(THREADS, 4) void hl_fused_kernel(
    const float* __restrict__ preds,
    const float* __restrict__ targets,
    float* __restrict__ out)
{
    extern __shared__ char dynbuf[];                 // STAGES * STAGE_BYTES
    const int tid = threadIdx.x;
    const int bid = blockIdx.x;

    const char* pc = (const char*)preds;
    const char* tc = (const char*)targets;

    // prologue: issue stages 0..STAGES-2
    #pragma unroll
    for (int s = 0; s < STAGES - 1; s++) {
        int tk = bid + s * NBLOCKS;
        if (tk < NTILES)
            issue_stage(dynbuf + s * STAGE_BYTES, pc, tc, tk, tid);
        cp_commit();
    }

    float l1_sum = 0.0f;
    float ov     = 0.0f;

    int k = 0;
    for (int tile = bid; tile < NTILES; tile += NBLOCKS, k++) {
        // issue stage k+STAGES-1 into buffer (k-1)%STAGES (released by
        // previous iteration's trailing __syncthreads)
        int tn = bid + (k + STAGES - 1) * NBLOCKS;
        if (tn < NTILES)
            issue_stage(dynbuf + ((k + STAGES - 1) % STAGES) * STAGE_BYTES, pc, tc, tn, tid);
        cp_commit();

        cp_wait_group<STAGES - 1>();                  // stage k's group complete
        __syncthreads();

        char* stage = dynbuf + (k % STAGES) * STAGE_BYTES;
        if (tid < TILE_ROWS)                          // 128 consumer threads
            row_math(stage + tid * 40, stage + ABYTES + tid * 40, l1_sum, ov);

        __syncthreads();                              // release buffer k%STAGES
    }

    // ---- block reduction ----
    #pragma unroll
    for (int off = 16; off > 0; off >>= 1) {
        l1_sum += __shfl_down_sync(0xFFFFFFFFu, l1_sum, off);
        ov     += __shfl_down_sync(0xFFFFFFFFu, ov, off);
    }
    __shared__ float warp_l1[THREADS / 32];
    __shared__ float warp_ov[THREADS / 32];
    const int lane = tid & 31;
    const int wid  = tid >> 5;
    if (lane == 0) { warp_l1[wid] = l1_sum; warp_ov[wid] = ov; }
    __syncthreads();

    if (wid == 0) {
        float a = (lane < THREADS / 32) ? warp_l1[lane] : 0.0f;
        float b = (lane < THREADS / 32) ? warp_ov[lane] : 0.0f;
        #pragma unroll
        for (int off = 4; off > 0; off >>= 1) {
            a += __shfl_down_sync(0xFFFFFFFFu, a, off);
            b += __shfl_down_sync(0xFFFFFFFFu, b, off);
        }
        if (lane == 0) {
            atomicAdd(&g_acc[0], (double)a);
            atomicAdd(&g_acc[1], (double)b);
            __threadfence();
            unsigned int ticket = atomicAdd(&g_ticket, 1u);
            if (ticket == (unsigned int)(NBLOCKS - 1)) {
                double s0 = *((volatile double*)&g_acc[0]);
                double s1 = *((volatile double*)&g_acc[1]);
                double param_loss = s0 / ((double)NROWS * 10.0);
                double mean_ov    = s1 / (double)NROWS;
                out[0] = (float)(param_loss + 0.5 * (1.0 - mean_ov));
                *((volatile double*)&g_acc[0]) = 0.0;
                *((volatile double*)&g_acc[1]) = 0.0;
                __threadfence();
                g_ticket = 0;
                __threadfence();
            }
        }
    }
}

extern "C" void kernel_launch(void* const* d_in, const int* in_sizes, int n_in,
                              void* d_out, int out_size) {
    const float* preds   = (const float*)d_in[0];
    const float* targets = (const float*)d_in[1];
    float* out = (float*)d_out;

    static bool attr_set = false;
    if (!attr_set) {
        cudaFuncSetAttribute(hl_fused_kernel,
                             cudaFuncAttributeMaxDynamicSharedMemorySize, SMEM_DYN);
        attr_set = true;
    }
    hl_fused_kernel<<<NBLOCKS, THREADS, SMEM_DYN>>>(preds, targets, out);
}